// round 6
// baseline (speedup 1.0000x reference)
#include <cuda_runtime.h>
#include <cuda_bf16.h>
#include <math.h>

#define Bz   32
#define Tz   512
#define INz  256
#define Hz   1024
#define G4z  4096
#define OUTz 256
#define Mz   (Bz * Tz)          // 16384

#define RBLK 128                 // recurrent blocks (1/SM, all co-resident)
#define SMEM_REC ((32*1024 + 2*128*32 + 32*32) * 4)   // 167936 B

// ------------------------- device scratch (no allocs allowed) -------------------
static __device__ float    g_xw [(size_t)Mz * G4z];   // 256 MB
static __device__ float    g_hs0[(size_t)Mz * Hz];    // 64 MB
static __device__ float    g_hs1[(size_t)Mz * Hz];    // 64 MB
static __device__ float    g_hbuf[2 * Hz * Bz];       // double-buffered h, [parity][k][b]
static __device__ unsigned g_arrive[RBLK];
static __device__ unsigned g_gen2;

// ---------------------------------------------------------------------------------
// Tiled fp32 GEMM: O[m][n] = sum_k A[m][k]*W[n][k] + bias1[n] (+bias2[n])
// amode 0: A row m at A + m*K        (row-major [M][K])
// amode 1: A = input_seq [b][t][k], row m=(t*32+b) -> offset ((m&31)*Tz + (m>>5))*K
// omode 0: O row-major [M][N]
// omode 1: O = out[b][t][n], row m=(t*32+b) -> offset ((m&31)*Tz + (m>>5))*N
// ---------------------------------------------------------------------------------
__global__ void __launch_bounds__(256) gemm64(
    const float* __restrict__ A, const float* __restrict__ W,
    const float* __restrict__ bias1, const float* __restrict__ bias2,
    float* __restrict__ O, int N, int K, int amode, int omode)
{
    __shared__ float As[16][68];
    __shared__ float Bs[16][68];

    const int tid = threadIdx.x;
    const int bm = blockIdx.y * 64;
    const int bn = blockIdx.x * 64;
    const int lr = tid >> 2;          // 0..63
    const int lk = (tid & 3) * 4;     // 0,4,8,12
    const int ty = tid >> 4;          // 0..15
    const int tx = tid & 15;          // 0..15

    float acc[4][4];
#pragma unroll
    for (int i = 0; i < 4; i++)
#pragma unroll
        for (int j = 0; j < 4; j++) acc[i][j] = 0.f;

    const int mrow = bm + lr;
    long arow;
    if (amode == 1) {
        const int b = mrow & 31, t = mrow >> 5;
        arow = ((long)b * Tz + t) * (long)K;
    } else {
        arow = (long)mrow * K;
    }
    const float* __restrict__ wrow = W + (long)(bn + lr) * K;

    for (int k0 = 0; k0 < K; k0 += 16) {
        float4 av = *(const float4*)(A + arow + k0 + lk);
        float4 bv = *(const float4*)(wrow + k0 + lk);
        As[lk + 0][lr] = av.x; As[lk + 1][lr] = av.y;
        As[lk + 2][lr] = av.z; As[lk + 3][lr] = av.w;
        Bs[lk + 0][lr] = bv.x; Bs[lk + 1][lr] = bv.y;
        Bs[lk + 2][lr] = bv.z; Bs[lk + 3][lr] = bv.w;
        __syncthreads();
#pragma unroll
        for (int k = 0; k < 16; k++) {
            float4 a4 = *(const float4*)&As[k][ty * 4];
            float4 b4 = *(const float4*)&Bs[k][tx * 4];
            float ar[4] = {a4.x, a4.y, a4.z, a4.w};
            float br[4] = {b4.x, b4.y, b4.z, b4.w};
#pragma unroll
            for (int i = 0; i < 4; i++)
#pragma unroll
                for (int j = 0; j < 4; j++)
                    acc[i][j] += ar[i] * br[j];
        }
        __syncthreads();
    }

#pragma unroll
    for (int i = 0; i < 4; i++) {
        const int m = bm + ty * 4 + i;
#pragma unroll
        for (int j = 0; j < 4; j++) {
            const int n = bn + tx * 4 + j;
            float bb = bias1[n];
            if (bias2) bb += bias2[n];
            const float v = acc[i][j] + bb;
            if (omode == 0) {
                O[(long)m * N + n] = v;
            } else {
                const int b = m & 31, t = m >> 5;
                O[((long)b * Tz + t) * (long)N + n] = v;
            }
        }
    }
}

// ---------------------------------------------------------------------------------
// Persistent LSTM recurrence for one layer.
// Grid = 128 blocks x 256 threads. Block bid owns h-units u0..u0+7 (u0 = bid*8),
// i.e. gate rows {g*1024 + u0 + j : g in 0..3, j in 0..7}, cached in smem for all
// 512 steps. Cross-block h via g_hbuf (L2, .cg ops) + flag-array grid barrier.
// ---------------------------------------------------------------------------------
__device__ __forceinline__ float sigm(float x) { return 1.0f / (1.0f + __expf(-x)); }

__global__ void __launch_bounds__(256, 1) lstm_rec(
    const float* __restrict__ xw,      // [T*B][4096], row m = t*32+b
    const float* __restrict__ Whh,     // [4096][1024]
    float* __restrict__ hs_out)        // [T*B][1024], row m = t*32+b
{
    extern __shared__ float smem[];
    float* Ws  = smem;                  // [32][1024]
    float* hsb = smem + 32 * 1024;      // [2][128][32]
    float* gs  = hsb + 2 * 128 * 32;    // [32][32]  (gate-row r, batch b)
    __shared__ unsigned s_base;

    const int tid = threadIdx.x;
    const int bid = blockIdx.x;
    const int u0  = bid * 8;

    // accumulation mapping: gate-row r, batches b0..b0+3
    const int r    = tid >> 3;          // 0..31
    const int b0   = (tid & 7) * 4;     // 0,4,...,28
    const int gsel = r >> 3;            // gate 0..3
    const int jsel = r & 7;             // unit within block
    const long col = (long)gsel * 1024 + u0 + jsel;   // column in xw

    // cell mapping: one (unit, batch) per thread
    const int cj = tid >> 5;            // 0..7
    const int cb = tid & 31;            // 0..31

    // load W_hh rows into smem (once)
    for (int rr = 0; rr < 32; rr++) {
        const long grow = (long)(rr >> 3) * 1024 + u0 + (rr & 7);
        const float4 v = __ldg((const float4*)(Whh + grow * 1024 + tid * 4));
        *(float4*)&Ws[rr * 1024 + tid * 4] = v;
    }
    if (tid == 0) s_base = *(volatile unsigned*)&g_gen2;
    __syncthreads();
    const unsigned base = s_base;

    float c = 0.f;

    for (int t = 0; t < Tz; t++) {
        // prefetch this step's xw contributions (independent of h)
        float xwv[4];
#pragma unroll
        for (int jj = 0; jj < 4; jj++)
            xwv[jj] = __ldg(&xw[((long)t * 32 + b0 + jj) * 4096 + col]);

        float acc[4] = {0.f, 0.f, 0.f, 0.f};

        if (t > 0) {
            const float* __restrict__ hsrc = g_hbuf + ((t + 1) & 1) * (Hz * Bz);
            float4 tmp[4];
#pragma unroll
            for (int i = 0; i < 4; i++)
                tmp[i] = __ldcg((const float4*)(hsrc + (i * 256 + tid) * 4));

#pragma unroll 1
            for (int kc = 0; kc < 8; kc++) {
                float* hdst = hsb + (kc & 1) * 4096;
#pragma unroll
                for (int i = 0; i < 4; i++)
                    *(float4*)&hdst[(i * 256 + tid) * 4] = tmp[i];
                __syncthreads();
                if (kc < 7) {
#pragma unroll
                    for (int i = 0; i < 4; i++)
                        tmp[i] = __ldcg((const float4*)(hsrc + (kc + 1) * 4096 + (i * 256 + tid) * 4));
                }
                const float* __restrict__ wr = Ws + r * 1024 + kc * 128;
#pragma unroll 4
                for (int k4 = 0; k4 < 128; k4 += 4) {
                    const float4 wv = *(const float4*)&wr[k4];
                    float4 hv;
                    hv = *(const float4*)&hdst[(k4 + 0) * 32 + b0];
                    acc[0] += wv.x * hv.x; acc[1] += wv.x * hv.y;
                    acc[2] += wv.x * hv.z; acc[3] += wv.x * hv.w;
                    hv = *(const float4*)&hdst[(k4 + 1) * 32 + b0];
                    acc[0] += wv.y * hv.x; acc[1] += wv.y * hv.y;
                    acc[2] += wv.y * hv.z; acc[3] += wv.y * hv.w;
                    hv = *(const float4*)&hdst[(k4 + 2) * 32 + b0];
                    acc[0] += wv.z * hv.x; acc[1] += wv.z * hv.y;
                    acc[2] += wv.z * hv.z; acc[3] += wv.z * hv.w;
                    hv = *(const float4*)&hdst[(k4 + 3) * 32 + b0];
                    acc[0] += wv.w * hv.x; acc[1] += wv.w * hv.y;
                    acc[2] += wv.w * hv.z; acc[3] += wv.w * hv.w;
                }
                __syncthreads();
            }
        }

        // gates -> smem
        *(float4*)&gs[r * 32 + b0] =
            make_float4(xwv[0] + acc[0], xwv[1] + acc[1], xwv[2] + acc[2], xwv[3] + acc[3]);
        __syncthreads();

        // cell update (one (unit,batch) per thread)
        const float gi = sigm (gs[( 0 + cj) * 32 + cb]);
        const float gf = sigm (gs[( 8 + cj) * 32 + cb]);
        const float gg = tanhf(gs[(16 + cj) * 32 + cb]);
        const float go = sigm (gs[(24 + cj) * 32 + cb]);
        c = gf * c + gi * gg;
        const float h = go * tanhf(c);

        // publish h (L2) and persist hidden state
        __stcg(&g_hbuf[(t & 1) * (Hz * Bz) + (u0 + cj) * 32 + cb], h);
        hs_out[((long)t * 32 + cb) * 1024 + u0 + cj] = h;

        // ---- grid barrier (flag-array) ----
        const unsigned target = base + (unsigned)t + 1u;
        __threadfence();
        __syncthreads();
        if (tid == 0)
            *(volatile unsigned*)&g_arrive[bid] = target;
        if (bid == 0) {
            if (tid < RBLK) {
                while ((int)(*(volatile unsigned*)&g_arrive[tid] - target) < 0) {}
            }
            __syncthreads();
            if (tid == 0) {
                __threadfence();
                *(volatile unsigned*)&g_gen2 = target;
            }
        }
        if (tid == 0) {
            while ((int)(*(volatile unsigned*)&g_gen2 - target) < 0) {}
        }
        __syncthreads();
    }
}

// ---------------------------------------------------------------------------------
extern "C" void kernel_launch(void* const* d_in, const int* in_sizes, int n_in,
                              void* d_out, int out_size)
{
    const float* x     = (const float*)d_in[0];
    const float* W_ih0 = (const float*)d_in[1];
    const float* W_hh0 = (const float*)d_in[2];
    const float* b_ih0 = (const float*)d_in[3];
    const float* b_hh0 = (const float*)d_in[4];
    const float* W_ih1 = (const float*)d_in[5];
    const float* W_hh1 = (const float*)d_in[6];
    const float* b_ih1 = (const float*)d_in[7];
    const float* b_hh1 = (const float*)d_in[8];
    const float* fc_w  = (const float*)d_in[9];
    const float* fc_b  = (const float*)d_in[10];
    float* out = (float*)d_out;

    float *xw, *hs0, *hs1;
    cudaGetSymbolAddress((void**)&xw,  g_xw);
    cudaGetSymbolAddress((void**)&hs0, g_hs0);
    cudaGetSymbolAddress((void**)&hs1, g_hs1);

    cudaFuncSetAttribute(lstm_rec, cudaFuncAttributeMaxDynamicSharedMemorySize, SMEM_REC);

    // 1) xW0 = x @ W_ih0^T + b_ih0 + b_hh0        [16384 x 4096], K=256
    gemm64<<<dim3(G4z / 64, Mz / 64), 256>>>(x, W_ih0, b_ih0, b_hh0, xw,
                                             G4z, INz, /*amode=*/1, /*omode=*/0);
    // 2) layer-0 recurrence -> hs0
    lstm_rec<<<RBLK, 256, SMEM_REC>>>(xw, W_hh0, hs0);
    // 3) xW1 = hs0 @ W_ih1^T + b_ih1 + b_hh1      [16384 x 4096], K=1024
    gemm64<<<dim3(G4z / 64, Mz / 64), 256>>>(hs0, W_ih1, b_ih1, b_hh1, xw,
                                             G4z, Hz, /*amode=*/0, /*omode=*/0);
    // 4) layer-1 recurrence -> hs1
    lstm_rec<<<RBLK, 256, SMEM_REC>>>(xw, W_hh1, hs1);
    // 5) out = hs1 @ fc_w^T + fc_b                [b][t][256], K=1024
    gemm64<<<dim3(OUTz / 64, Mz / 64), 256>>>(hs1, fc_w, fc_b, nullptr, out,
                                              OUTz, Hz, /*amode=*/0, /*omode=*/1);
}

// round 7
// speedup vs baseline: 2.3683x; 2.3683x over previous
#include <cuda_runtime.h>
#include <cuda_bf16.h>
#include <math.h>

#define Bz   32
#define Tz   512
#define INz  256
#define Hz   1024
#define G4z  4096
#define OUTz 256
#define Mz   (Bz * Tz)          // 16384

#define RBLK 128                 // recurrent blocks (1/SM, all co-resident)

// lstm_rec smem: WsT (swizzled k-major W_hh) + hsb (h chunks / slice partials) + gs
#define WST_WORDS  (1024 * 32)   // 131072 B
#define HSB_WORDS  (8192)        // 32768 B  (2x[128][32] staging, reused as [8][32][32] partials)
#define GS_WORDS   (1024)        // 4096 B
#define SMEM_REC   ((WST_WORDS + HSB_WORDS + GS_WORDS) * 4)   // 167936 B

#define GEMM_SMEM  (2 * 2 * 128 * 36 * 4)   // 73728 B (A+B, double buffered)

// ------------------------- device scratch (no allocs allowed) -------------------
static __device__ float    g_xw [(size_t)Mz * G4z];   // 256 MB
static __device__ float    g_hs0[(size_t)Mz * Hz];    // 64 MB
static __device__ float    g_hs1[(size_t)Mz * Hz];    // 64 MB
static __device__ float    g_hbuf[2 * Hz * Bz];       // double-buffered h, [parity][k][b]
static __device__ unsigned g_arrive[RBLK];
static __device__ unsigned g_gen2;

// ---------------------------------------------------------------------------------
// tf32 tensor-core GEMM: O[m][n] = sum_k A[m][k]*W[n][k] + bias1[n] (+bias2[n])
// Block tile 128x128, 8 warps (2x4), warp tile 64x32, k-chunk 32.
// amode 1: A = input_seq [b][t][k], row m=(t*32+b); amode 0: A row-major [M][K].
// omode 1: O = out[b][t][n], row m=(t*32+b);        omode 0: O row-major [M][N].
// ---------------------------------------------------------------------------------
__device__ __forceinline__ unsigned f2tf(float f) {
    unsigned u; asm("cvt.rna.tf32.f32 %0, %1;" : "=r"(u) : "f"(f)); return u;
}

#define MMA_TF32(d, a, b)                                                     \
    asm volatile("mma.sync.aligned.m16n8k8.row.col.f32.tf32.tf32.f32 "        \
        "{%0,%1,%2,%3}, {%4,%5,%6,%7}, {%8,%9}, {%0,%1,%2,%3};"               \
        : "+f"(d[0]), "+f"(d[1]), "+f"(d[2]), "+f"(d[3])                      \
        : "r"(a[0]), "r"(a[1]), "r"(a[2]), "r"(a[3]), "r"(b[0]), "r"(b[1]))

__global__ void __launch_bounds__(256) gemm_tf32(
    const float* __restrict__ A, const float* __restrict__ W,
    const float* __restrict__ bias1, const float* __restrict__ bias2,
    float* __restrict__ O, int N, int K, int amode, int omode)
{
    extern __shared__ unsigned gsm[];
    // layout: As[2][128*36], Bs[2][128*36]
    unsigned* Asm = gsm;
    unsigned* Bsm = gsm + 2 * 128 * 36;

    const int tid  = threadIdx.x;
    const int bm   = blockIdx.y * 128;
    const int bn   = blockIdx.x * 128;
    const int wid  = tid >> 5, lane = tid & 31;
    const int wm   = (wid >> 2) * 64;     // warp M offset (0 or 64)
    const int wn   = (wid & 3) * 32;      // warp N offset
    const int g    = lane >> 2;           // 0..7
    const int t4   = lane & 3;            // 0..3

    // loader: thread -> (row lr, k-half lh)
    const int lr = tid >> 1;              // 0..127
    const int lh = (tid & 1) * 16;        // 0 or 16

    long arow;
    {
        const int m = bm + lr;
        if (amode == 1) { const int b = m & 31, t = m >> 5; arow = ((long)b * Tz + t) * (long)K; }
        else            { arow = (long)m * K; }
    }
    const long brow = (long)(bn + lr) * K;

    float acc[4][4][4];
#pragma unroll
    for (int i = 0; i < 4; i++)
#pragma unroll
        for (int j = 0; j < 4; j++)
#pragma unroll
            for (int q = 0; q < 4; q++) acc[i][j][q] = 0.f;

    float4 av[4], bv[4];
#pragma unroll
    for (int q = 0; q < 4; q++) {
        av[q] = __ldg((const float4*)(A + arow + lh + q * 4));
        bv[q] = __ldg((const float4*)(W + brow + lh + q * 4));
    }

    const int nc = K >> 5;
    for (int c = 0; c < nc; c++) {
        unsigned* as = Asm + (c & 1) * (128 * 36);
        unsigned* bs = Bsm + (c & 1) * (128 * 36);
        const int sb = lr * 36 + lh;
#pragma unroll
        for (int q = 0; q < 4; q++) {
            uint4 ua = make_uint4(f2tf(av[q].x), f2tf(av[q].y), f2tf(av[q].z), f2tf(av[q].w));
            uint4 ub = make_uint4(f2tf(bv[q].x), f2tf(bv[q].y), f2tf(bv[q].z), f2tf(bv[q].w));
            *(uint4*)&as[sb + q * 4] = ua;
            *(uint4*)&bs[sb + q * 4] = ub;
        }
        __syncthreads();

        if (c + 1 < nc) {
            const long ko = (long)(c + 1) * 32 + lh;
#pragma unroll
            for (int q = 0; q < 4; q++) {
                av[q] = __ldg((const float4*)(A + arow + ko + q * 4));
                bv[q] = __ldg((const float4*)(W + brow + ko + q * 4));
            }
        }

#pragma unroll
        for (int k8 = 0; k8 < 32; k8 += 8) {
            unsigned af[4][4], bf[4][2];
#pragma unroll
            for (int fm = 0; fm < 4; fm++) {
                const int r0 = wm + fm * 16 + g;
                af[fm][0] = as[r0 * 36 + k8 + t4];
                af[fm][1] = as[(r0 + 8) * 36 + k8 + t4];
                af[fm][2] = as[r0 * 36 + k8 + t4 + 4];
                af[fm][3] = as[(r0 + 8) * 36 + k8 + t4 + 4];
            }
#pragma unroll
            for (int fn = 0; fn < 4; fn++) {
                const int n0 = wn + fn * 8 + g;
                bf[fn][0] = bs[n0 * 36 + k8 + t4];
                bf[fn][1] = bs[n0 * 36 + k8 + t4 + 4];
            }
#pragma unroll
            for (int fm = 0; fm < 4; fm++)
#pragma unroll
                for (int fn = 0; fn < 4; fn++)
                    MMA_TF32(acc[fm][fn], af[fm], bf[fn]);
        }
        __syncthreads();
    }

    // epilogue: d frags: rows (r0, r0+8), cols (n0, n0+1)
#pragma unroll
    for (int fm = 0; fm < 4; fm++) {
        const int r0 = bm + wm + fm * 16 + g;
#pragma unroll
        for (int fn = 0; fn < 4; fn++) {
            const int n0 = bn + wn + fn * 8 + t4 * 2;
            float b0v = bias1[n0], b1v = bias1[n0 + 1];
            if (bias2) { b0v += bias2[n0]; b1v += bias2[n0 + 1]; }
            const float2 v0 = make_float2(acc[fm][fn][0] + b0v, acc[fm][fn][1] + b1v);
            const float2 v1 = make_float2(acc[fm][fn][2] + b0v, acc[fm][fn][3] + b1v);
            if (omode == 0) {
                *(float2*)&O[(long)r0 * N + n0]       = v0;
                *(float2*)&O[(long)(r0 + 8) * N + n0] = v1;
            } else {
                int b_ = r0 & 31, t_ = r0 >> 5;
                *(float2*)&O[((long)b_ * Tz + t_) * N + n0] = v0;
                b_ = (r0 + 8) & 31; t_ = (r0 + 8) >> 5;
                *(float2*)&O[((long)b_ * Tz + t_) * N + n0] = v1;
            }
        }
    }
}

// ---------------------------------------------------------------------------------
// Persistent LSTM recurrence, FFMA-bound version.
// Block bid owns h-units u0..u0+7 (32 gate rows). Per thread: 4 rows x 8 batches x
// 16-k slice per 128-k chunk (8 chunks), 32 accumulators. W_hh cached in smem
// k-major with rotation swizzle (rr + 4k) & 31. Slice partials reduced via smem.
// ---------------------------------------------------------------------------------
__device__ __forceinline__ float sigm(float x) { return 1.0f / (1.0f + __expf(-x)); }

__global__ void __launch_bounds__(256, 1) lstm_rec(
    const float* __restrict__ xw,      // [T*B][4096], row m = t*32+b
    const float* __restrict__ Whh,     // [4096][1024]
    float* __restrict__ hs_out)        // [T*B][1024], row m = t*32+b
{
    extern __shared__ float smem[];
    float* WsT = smem;                         // swizzled [1024 k][32 rr]
    float* hsb = smem + WST_WORDS;             // staging / partials
    float* gs  = smem + WST_WORDS + HSB_WORDS; // [32 rr][32 b] swizzled
    __shared__ unsigned s_base;

    const int tid = threadIdx.x;
    const int bid = blockIdx.x;
    const int u0  = bid * 8;

    // compute mapping: warp = k-slice, lane -> (row group, batch group)
    const int s   = tid >> 5;            // 0..7
    const int p   = tid & 31;
    const int rg4 = (p >> 2) * 4;        // rows rg4..rg4+3
    const int bg8 = (p & 3) * 8;         // batches bg8..bg8+7

    // reduction mapping: thread -> (row rr_r, batches b_r..b_r+3)
    const int rr_r = tid >> 3;           // 0..31
    const int b_r  = (tid & 7) * 4;
    const long col_r = (long)(rr_r >> 3) * 1024 + u0 + (rr_r & 7);

    // cell mapping: thread -> (unit cj, batch cb)
    const int cj = tid >> 5, cb = tid & 31;

    // ---- load W_hh rows into swizzled k-major smem (one-time) ----
    for (int rr = 0; rr < 32; rr++) {
        const long grow = (long)(rr >> 3) * 1024 + u0 + (rr & 7);
        const float4 v = __ldg((const float4*)(Whh + grow * 1024 + tid * 4));
        const int kb = tid * 4;
        WsT[(kb + 0) * 32 + ((rr + 4 * (kb + 0)) & 31)] = v.x;
        WsT[(kb + 1) * 32 + ((rr + 4 * (kb + 1)) & 31)] = v.y;
        WsT[(kb + 2) * 32 + ((rr + 4 * (kb + 2)) & 31)] = v.z;
        WsT[(kb + 3) * 32 + ((rr + 4 * (kb + 3)) & 31)] = v.w;
    }
    if (tid == 0) s_base = *(volatile unsigned*)&g_gen2;
    __syncthreads();
    const unsigned base = s_base;

    float cst = 0.f;

#pragma unroll 1
    for (int t = 0; t < Tz; t++) {
        // prefetch xw for this thread's reduction outputs
        float xwv[4];
#pragma unroll
        for (int q = 0; q < 4; q++)
            xwv[q] = __ldg(&xw[((long)t * 32 + b_r + q) * 4096 + col_r]);

        if (t > 0) {
            float acc[4][8];
#pragma unroll
            for (int i = 0; i < 4; i++)
#pragma unroll
                for (int j = 0; j < 8; j++) acc[i][j] = 0.f;

            const float* __restrict__ hsrc = g_hbuf + ((t + 1) & 1) * (Hz * Bz);
            float4 tmp[4];
#pragma unroll
            for (int i = 0; i < 4; i++)
                tmp[i] = __ldcg((const float4*)(hsrc + (i * 256 + tid) * 4));

#pragma unroll 1
            for (int kc = 0; kc < 8; kc++) {
                float* hch = hsb + (kc & 1) * 4096;
#pragma unroll
                for (int i = 0; i < 4; i++)
                    *(float4*)&hch[(i * 256 + tid) * 4] = tmp[i];
                __syncthreads();
                if (kc < 7) {
#pragma unroll
                    for (int i = 0; i < 4; i++)
                        tmp[i] = __ldcg((const float4*)(hsrc + (kc + 1) * 4096 + (i * 256 + tid) * 4));
                }
                const int kbase  = kc * 128 + s * 16;   // global k for this slice
                const int klocal = s * 16;              // within staged chunk
#pragma unroll
                for (int kk = 0; kk < 16; kk++) {
                    const float4 w4 = *(const float4*)&WsT[(kbase + kk) * 32 + ((rg4 + 4 * kk) & 31)];
                    const float4 ha = *(const float4*)&hch[(klocal + kk) * 32 + bg8];
                    const float4 hb = *(const float4*)&hch[(klocal + kk) * 32 + bg8 + 4];
                    const float wv[4] = {w4.x, w4.y, w4.z, w4.w};
                    const float hv[8] = {ha.x, ha.y, ha.z, ha.w, hb.x, hb.y, hb.z, hb.w};
#pragma unroll
                    for (int i = 0; i < 4; i++)
#pragma unroll
                        for (int j = 0; j < 8; j++)
                            acc[i][j] += wv[i] * hv[j];
                }
                __syncthreads();
            }

            // write slice partials into hsb (reused as red[8][32][32], swizzled)
#pragma unroll
            for (int i = 0; i < 4; i++) {
                const int rr = rg4 + i;
                const int bw = s * 1024 + rr * 32;
                *(float4*)&hsb[bw + ((bg8 + 4 * rr) & 31)] =
                    make_float4(acc[i][0], acc[i][1], acc[i][2], acc[i][3]);
                *(float4*)&hsb[bw + ((bg8 + 4 + 4 * rr) & 31)] =
                    make_float4(acc[i][4], acc[i][5], acc[i][6], acc[i][7]);
            }
        }
        __syncthreads();

        // reduce 8 slice partials + xw -> gates
        float4 sum = make_float4(xwv[0], xwv[1], xwv[2], xwv[3]);
        if (t > 0) {
            const int sw = rr_r * 32 + ((b_r + 4 * rr_r) & 31);
#pragma unroll
            for (int ss = 0; ss < 8; ss++) {
                const float4 v = *(const float4*)&hsb[ss * 1024 + sw];
                sum.x += v.x; sum.y += v.y; sum.z += v.z; sum.w += v.w;
            }
        }
        *(float4*)&gs[rr_r * 32 + ((b_r + 4 * rr_r) & 31)] = sum;
        __syncthreads();

        // cell update (unit cj, batch cb); gate rows: i=cj, f=8+cj, g=16+cj, o=24+cj
        const int r_i = cj, r_f = 8 + cj, r_g = 16 + cj, r_o = 24 + cj;
        const float gi = sigm (gs[r_i * 32 + ((cb + 4 * r_i) & 31)]);
        const float gf = sigm (gs[r_f * 32 + ((cb + 4 * r_f) & 31)]);
        const float gg = tanhf(gs[r_g * 32 + ((cb + 4 * r_g) & 31)]);
        const float go = sigm (gs[r_o * 32 + ((cb + 4 * r_o) & 31)]);
        cst = gf * cst + gi * gg;
        const float h = go * tanhf(cst);

        __stcg(&g_hbuf[(t & 1) * (Hz * Bz) + (u0 + cj) * 32 + cb], h);
        hs_out[((long)t * 32 + cb) * 1024 + u0 + cj] = h;

        // ---- grid barrier (flag-array) ----
        const unsigned target = base + (unsigned)t + 1u;
        __threadfence();
        __syncthreads();
        if (tid == 0)
            *(volatile unsigned*)&g_arrive[bid] = target;
        if (bid == 0) {
            if (tid < RBLK) {
                while ((int)(*(volatile unsigned*)&g_arrive[tid] - target) < 0) {}
            }
            __syncthreads();
            if (tid == 0) {
                __threadfence();
                *(volatile unsigned*)&g_gen2 = target;
            }
        }
        if (tid == 0) {
            while ((int)(*(volatile unsigned*)&g_gen2 - target) < 0) {}
        }
        __syncthreads();
    }
}

// ---------------------------------------------------------------------------------
extern "C" void kernel_launch(void* const* d_in, const int* in_sizes, int n_in,
                              void* d_out, int out_size)
{
    const float* x     = (const float*)d_in[0];
    const float* W_ih0 = (const float*)d_in[1];
    const float* W_hh0 = (const float*)d_in[2];
    const float* b_ih0 = (const float*)d_in[3];
    const float* b_hh0 = (const float*)d_in[4];
    const float* W_ih1 = (const float*)d_in[5];
    const float* W_hh1 = (const float*)d_in[6];
    const float* b_ih1 = (const float*)d_in[7];
    const float* b_hh1 = (const float*)d_in[8];
    const float* fc_w  = (const float*)d_in[9];
    const float* fc_b  = (const float*)d_in[10];
    float* out = (float*)d_out;

    float *xw, *hs0, *hs1;
    cudaGetSymbolAddress((void**)&xw,  g_xw);
    cudaGetSymbolAddress((void**)&hs0, g_hs0);
    cudaGetSymbolAddress((void**)&hs1, g_hs1);

    cudaFuncSetAttribute(lstm_rec, cudaFuncAttributeMaxDynamicSharedMemorySize, SMEM_REC);
    cudaFuncSetAttribute(gemm_tf32, cudaFuncAttributeMaxDynamicSharedMemorySize, GEMM_SMEM);

    // 1) xW0 = x @ W_ih0^T + b_ih0 + b_hh0        [16384 x 4096], K=256
    gemm_tf32<<<dim3(G4z / 128, Mz / 128), 256, GEMM_SMEM>>>(
        x, W_ih0, b_ih0, b_hh0, xw, G4z, INz, /*amode=*/1, /*omode=*/0);
    // 2) layer-0 recurrence -> hs0
    lstm_rec<<<RBLK, 256, SMEM_REC>>>(xw, W_hh0, hs0);
    // 3) xW1 = hs0 @ W_ih1^T + b_ih1 + b_hh1      [16384 x 4096], K=1024
    gemm_tf32<<<dim3(G4z / 128, Mz / 128), 256, GEMM_SMEM>>>(
        hs0, W_ih1, b_ih1, b_hh1, xw, G4z, Hz, /*amode=*/0, /*omode=*/0);
    // 4) layer-1 recurrence -> hs1
    lstm_rec<<<RBLK, 256, SMEM_REC>>>(xw, W_hh1, hs1);
    // 5) out = hs1 @ fc_w^T + fc_b                [b][t][256], K=1024
    gemm_tf32<<<dim3(OUTz / 128, Mz / 128), 256, GEMM_SMEM>>>(
        hs1, fc_w, fc_b, nullptr, out, OUTz, Hz, /*amode=*/0, /*omode=*/1);
}